// round 9
// baseline (speedup 1.0000x reference)
#include <cuda_runtime.h>
#include <cstdint>
#include <cstddef>

// Problem constants
#define B_      64
#define T_      1024
#define F_      256
#define U_      512
#define G3_     1536
#define SIG_    31

// Persistent kernel config: 2 CTAs per SM, each CTA owns 2 units.
#define GRID_    256
#define THREADS_ 256
#define KTOT_    768         // K = 256 (x) + 512 (h)
#define NCOL_    6           // 3 gates x 2 units per CTA
#define RGRP_    8           // reduction groups after shuffle fold
#define WROW_    12          // w2 floats per k-row (6 cols duplicated)
#define FB_      (F_ * B_)
#define UB_      (U_ * B_)
#define RSZ_     (RGRP_ * NCOL_ * B_)   // floats per rs buffer (3072)

// Scratch (static __device__ arrays: no allocation)
__device__ __align__(256) float g_f_all[(size_t)T_ * UB_]; // sigmoid(f_pre) [t][u][b]
__device__ __align__(256) float g_x[(size_t)T_ * FB_];     // x transposed [t][f][b]
__device__ __align__(256) float g_h[2][UB_];               // ping-pong h [u][b]
__device__ unsigned int g_bar;

__device__ __forceinline__ void fma2(unsigned long long& a, unsigned long long x,
                                     unsigned long long w) {
    asm("fma.rn.f32x2 %0, %1, %2, %0;" : "+l"(a) : "l"(x), "l"(w));
}
__device__ __forceinline__ float2 up2(unsigned long long v) {
    float2 r; asm("mov.b64 {%0, %1}, %2;" : "=f"(r.x), "=f"(r.y) : "l"(v)); return r;
}
__device__ __forceinline__ float tanh_fast(float x) {
    float y; asm("tanh.approx.f32 %0, %1;" : "=f"(y) : "f"(x)); return y;
}
__device__ __forceinline__ float sigmoid_fast(float x) {
    return 0.5f * tanh_fast(0.5f * x) + 0.5f;
}
// 16B global load, L2-coherent (bypass L1) -> two 64-bit regs
__device__ __forceinline__ void ldg_cg2(const float* p, unsigned long long& a,
                                        unsigned long long& b) {
    asm volatile("ld.global.cg.v2.u64 {%0, %1}, [%2];" : "=l"(a), "=l"(b) : "l"(p));
}
// 16B global load, read-only path
__device__ __forceinline__ void ldg_nc2(const float* p, unsigned long long& a,
                                        unsigned long long& b) {
    asm("ld.global.nc.v2.u64 {%0, %1}, [%2];" : "=l"(a), "=l"(b) : "l"(p));
}

// fpre: f_all[t][u][b] = sigmoid(sig . fk + b_f); transposes x to g_x[t][f][b];
// resets barrier counter + initial h each launch (graph replays).
__global__ void fpre_kernel(const float* __restrict__ inputs,
                            const float* __restrict__ sig,
                            const float* __restrict__ fk,
                            const float* __restrict__ bias) {
    extern __shared__ float xs[];            // [256][65] transpose tile
    __shared__ float sig_s[B_][33];
    const int t = blockIdx.x, tid = threadIdx.x;
    if (t == 0 && tid == 0) g_bar = 0u;
    if (t < 128) g_h[0][t * 256 + tid] = 0.f;

    for (int i = tid; i < B_ * F_; i += 256) {
        int b = i >> 8, f = i & 255;
        xs[f * 65 + b] = inputs[((size_t)b * T_ + t) * F_ + f];
    }
    for (int i = tid; i < B_ * SIG_; i += 256) {
        int b = i / SIG_, d = i - b * SIG_;
        sig_s[b][d] = sig[((size_t)b * T_ + t) * SIG_ + d];
    }
    __syncthreads();
    for (int j = tid; j < FB_; j += 256) {
        int f = j >> 6, b = j & 63;
        g_x[(size_t)t * FB_ + j] = xs[f * 65 + b];
    }
    size_t base = (size_t)t * UB_;
    for (int idx = tid; idx < UB_; idx += 256) {
        int u = idx >> 6, b = idx & 63;
        float acc = bias[U_ + u];
        #pragma unroll
        for (int d = 0; d < SIG_; d++) acc += sig_s[b][d] * __ldg(&fk[d * U_ + u]);
        g_f_all[base + idx] = 1.f / (1.f + expf(-acc));
    }
}

// Persistent recurrence. 256 CTAs x 256 threads (2 CTAs per SM) — two
// independent lock-step pipelines per SM hide each other's sync/barrier/LDG
// stalls. Register-direct activations; poll overlapped under x-part; rs
// double-buffered (2 syncthreads + 1 named barrier per step).
__global__ void __launch_bounds__(THREADS_, 2)
lstm_kernel(const float* __restrict__ ik, const float* __restrict__ rk,
            const float* __restrict__ bias, float* __restrict__ out) {
    extern __shared__ float smem[];
    float* w2  = smem;                         // [768][12] dup-pair weights (36864 B)
    float* rs0 = smem + KTOT_ * WROW_;         // rs parity 0 (12288 B)
    float* rs1 = rs0 + RSZ_;                   // rs parity 1 (12288 B)

    const int tid  = threadIdx.x;
    const int ublk = blockIdx.x * 2;

    // Weights: rows 0..255 = input_kernel, 256..767 = recurrent_kernel.
    // col(j): gate g=j>>1, unit uu=j&1 -> global col g*512 + ublk + uu
    for (int idx = tid; idx < KTOT_ * NCOL_; idx += THREADS_) {
        int k = idx / NCOL_, j = idx - k * NCOL_;
        int col = (j >> 1) * U_ + ublk + (j & 1);
        float w = (k < F_) ? ik[(size_t)k * G3_ + col]
                           : rk[(size_t)(k - F_) * G3_ + col];
        w2[idx * 2] = w; w2[idx * 2 + 1] = w;
    }

    const int b4 = tid & 15;            // batch group (4 batches = 2 f32x2)
    const int ks = tid >> 4;            // 0..15 K-split
    const int fb = tid & 63, fu = (tid >> 6) & 1;
    const int u_g = ublk + fu;
    float bi = 0.f, bc = 0.f, bo = 0.f;
    if (tid < 128) {
        bi = bias[u_g]; bc = bias[2 * U_ + u_g]; bo = bias[3 * U_ + u_g];
    }

    // Per-thread slices: x rows ks*16..+15, h rows ks*32..+31
    const float* xbase = g_x + (size_t)(ks * 16) * B_ + b4 * 4;   // + t*FB_
    const int    hoff  = (ks * 32) * B_ + b4 * 4;                 // within g_h[p]
    const float* wx    = w2 + (ks * 16) * WROW_;
    const float* wh    = w2 + (F_ + ks * 32) * WROW_;

    float c_state = 0.f;
    float fval = (tid < 128) ? __ldg(&g_f_all[(size_t)u_g * B_ + fb]) : 0.f;
    __syncthreads();   // weights visible

    for (int t = 0; t < T_; t++) {
        unsigned long long acc[NCOL_][2];
        #pragma unroll
        for (int j = 0; j < NCOL_; j++) { acc[j][0] = 0ull; acc[j][1] = 0ull; }

        const float* xp = xbase + (size_t)t * FB_;
        const float* hp = g_h[t & 1] + hoff;
        float* rs = (t & 1) ? rs1 : rs0;

        // ---- Phase A: x-part (12 of 16 rows); tid0 polls the grid barrier ----
        unsigned long long xv0[8][2], xv1[8][2];
        #pragma unroll
        for (int j = 0; j < 8; j++) ldg_nc2(xp + j * B_, xv0[j][0], xv0[j][1]);
        #pragma unroll
        for (int j = 0; j < 8; j++) ldg_nc2(xp + (8 + j) * B_, xv1[j][0], xv1[j][1]);
        if (tid == 0 && t > 0) {
            const unsigned tgt = (unsigned)t * GRID_;
            unsigned v;
            do {
                asm volatile("ld.acquire.gpu.global.u32 %0, [%1];"
                             : "=r"(v) : "l"(&g_bar) : "memory");
            } while (v < tgt);
        }
        #pragma unroll
        for (int j = 0; j < 8; j++) {
            const ulonglong2* wr = (const ulonglong2*)(wx + j * WROW_);
            #pragma unroll
            for (int j2 = 0; j2 < 3; j2++) {
                ulonglong2 wv = wr[j2];
                fma2(acc[2 * j2    ][0], xv0[j][0], wv.x);
                fma2(acc[2 * j2    ][1], xv0[j][1], wv.x);
                fma2(acc[2 * j2 + 1][0], xv0[j][0], wv.y);
                fma2(acc[2 * j2 + 1][1], xv0[j][1], wv.y);
            }
        }
        #pragma unroll
        for (int j = 0; j < 4; j++) {
            const ulonglong2* wr = (const ulonglong2*)(wx + (8 + j) * WROW_);
            #pragma unroll
            for (int j2 = 0; j2 < 3; j2++) {
                ulonglong2 wv = wr[j2];
                fma2(acc[2 * j2    ][0], xv1[j][0], wv.x);
                fma2(acc[2 * j2    ][1], xv1[j][1], wv.x);
                fma2(acc[2 * j2 + 1][0], xv1[j][0], wv.y);
                fma2(acc[2 * j2 + 1][1], xv1[j][1], wv.y);
            }
        }
        __syncthreads();   // poll done -> h(t) globally visible

        // ---- Phase B: issue h loads; last 4 x rows as latency filler ----
        unsigned long long ha[8][2], hb[8][2];
        #pragma unroll
        for (int j = 0; j < 8; j++) ldg_cg2(hp + j * B_, ha[j][0], ha[j][1]);
        #pragma unroll
        for (int j = 0; j < 8; j++) ldg_cg2(hp + (8 + j) * B_, hb[j][0], hb[j][1]);
        #pragma unroll
        for (int j = 4; j < 8; j++) {
            const ulonglong2* wr = (const ulonglong2*)(wx + (8 + j) * WROW_);
            #pragma unroll
            for (int j2 = 0; j2 < 3; j2++) {
                ulonglong2 wv = wr[j2];
                fma2(acc[2 * j2    ][0], xv1[j][0], wv.x);
                fma2(acc[2 * j2    ][1], xv1[j][1], wv.x);
                fma2(acc[2 * j2 + 1][0], xv1[j][0], wv.y);
                fma2(acc[2 * j2 + 1][1], xv1[j][1], wv.y);
            }
        }
        // consume h rows 0..7, then reload group a with rows 16..23, etc.
        #pragma unroll
        for (int j = 0; j < 8; j++) {
            const ulonglong2* wr = (const ulonglong2*)(wh + j * WROW_);
            #pragma unroll
            for (int j2 = 0; j2 < 3; j2++) {
                ulonglong2 wv = wr[j2];
                fma2(acc[2 * j2    ][0], ha[j][0], wv.x);
                fma2(acc[2 * j2    ][1], ha[j][1], wv.x);
                fma2(acc[2 * j2 + 1][0], ha[j][0], wv.y);
                fma2(acc[2 * j2 + 1][1], ha[j][1], wv.y);
            }
        }
        #pragma unroll
        for (int j = 0; j < 8; j++) ldg_cg2(hp + (16 + j) * B_, ha[j][0], ha[j][1]);
        #pragma unroll
        for (int j = 0; j < 8; j++) {
            const ulonglong2* wr = (const ulonglong2*)(wh + (8 + j) * WROW_);
            #pragma unroll
            for (int j2 = 0; j2 < 3; j2++) {
                ulonglong2 wv = wr[j2];
                fma2(acc[2 * j2    ][0], hb[j][0], wv.x);
                fma2(acc[2 * j2    ][1], hb[j][1], wv.x);
                fma2(acc[2 * j2 + 1][0], hb[j][0], wv.y);
                fma2(acc[2 * j2 + 1][1], hb[j][1], wv.y);
            }
        }
        #pragma unroll
        for (int j = 0; j < 8; j++) ldg_cg2(hp + (24 + j) * B_, hb[j][0], hb[j][1]);
        #pragma unroll
        for (int j = 0; j < 8; j++) {
            const ulonglong2* wr = (const ulonglong2*)(wh + (16 + j) * WROW_);
            #pragma unroll
            for (int j2 = 0; j2 < 3; j2++) {
                ulonglong2 wv = wr[j2];
                fma2(acc[2 * j2    ][0], ha[j][0], wv.x);
                fma2(acc[2 * j2    ][1], ha[j][1], wv.x);
                fma2(acc[2 * j2 + 1][0], ha[j][0], wv.y);
                fma2(acc[2 * j2 + 1][1], ha[j][1], wv.y);
            }
        }
        #pragma unroll
        for (int j = 0; j < 8; j++) {
            const ulonglong2* wr = (const ulonglong2*)(wh + (24 + j) * WROW_);
            #pragma unroll
            for (int j2 = 0; j2 < 3; j2++) {
                ulonglong2 wv = wr[j2];
                fma2(acc[2 * j2    ][0], hb[j][0], wv.x);
                fma2(acc[2 * j2    ][1], hb[j][1], wv.x);
                fma2(acc[2 * j2 + 1][0], hb[j][0], wv.y);
                fma2(acc[2 * j2 + 1][1], hb[j][1], wv.y);
            }
        }

        // ---- Phase C: shuffle-fold ks pairs (lane^16), store 8 groups ----
        #pragma unroll
        for (int j = 0; j < NCOL_; j++) {
            #pragma unroll
            for (int p = 0; p < 2; p++) {
                float2 v = up2(acc[j][p]);
                v.x += __shfl_xor_sync(0xffffffffu, v.x, 16);
                v.y += __shfl_xor_sync(0xffffffffu, v.y, 16);
                if ((ks & 1) == 0)
                    *(float2*)&rs[((ks >> 1) * NCOL_ + j) * B_ + b4 * 4 + p * 2] = v;
            }
        }
        __syncthreads();   // rs visible to finalize threads

        // ---- Phase D: finalize (tid<128); others run ahead into next x-part ----
        if (tid < 128) {
            float si = 0.f, sc = 0.f, so = 0.f;
            #pragma unroll
            for (int p = 0; p < RGRP_; p++) {
                si += rs[(p * NCOL_     + fu) * B_ + fb];
                sc += rs[(p * NCOL_ + 2 + fu) * B_ + fb];
                so += rs[(p * NCOL_ + 4 + fu) * B_ + fb];
            }
            float ig = sigmoid_fast(si + bi);
            float cg = tanh_fast(sc + bc);
            float og = sigmoid_fast(so + bo);
            c_state = fval * c_state + ig * cg;
            float h = og * tanh_fast(c_state);
            if (t == T_ - 1) {
                out[fb * U_ + u_g] = h;
            } else {
                g_h[(t + 1) & 1][u_g * B_ + fb] = h;
                fval = __ldg(&g_f_all[(size_t)(t + 1) * UB_ + u_g * B_ + fb]);
                asm volatile("bar.sync 1, 128;" ::: "memory");  // all h stores done
                if (tid == 0) {
                    asm volatile("red.release.gpu.global.add.u32 [%0], %1;"
                                 :: "l"(&g_bar), "r"(1u) : "memory");
                }
            }
        }
        // no trailing sync: rs double-buffered; next phase-A sync re-converges.
    }
}

extern "C" void kernel_launch(void* const* d_in, const int* in_sizes, int n_in,
                              void* d_out, int out_size) {
    const float* inputs = (const float*)d_in[0];  // [64,1024,256]
    const float* sig    = (const float*)d_in[1];  // [64,1024,31]
    const float* fk     = (const float*)d_in[2];  // [31,512]
    const float* ik     = (const float*)d_in[3];  // [256,1536]
    const float* rk     = (const float*)d_in[4];  // [512,1536]
    const float* bias   = (const float*)d_in[5];  // [2048]
    float* out = (float*)d_out;                   // [64,512]
    (void)in_sizes; (void)n_in; (void)out_size;

    const int fpre_smem = 256 * 65 * 4;
    cudaFuncSetAttribute(fpre_kernel, cudaFuncAttributeMaxDynamicSharedMemorySize,
                         fpre_smem);
    const int smem_bytes = (KTOT_ * WROW_ + 2 * RSZ_) * 4;  // 61440 B per CTA
    cudaFuncSetAttribute(lstm_kernel, cudaFuncAttributeMaxDynamicSharedMemorySize,
                         smem_bytes);

    fpre_kernel<<<T_, 256, fpre_smem>>>(inputs, sig, fk, bias);
    lstm_kernel<<<GRID_, THREADS_, smem_bytes>>>(ik, rk, bias, out);
}